// round 11
// baseline (speedup 1.0000x reference)
#include <cuda_runtime.h>
#include <cuda_bf16.h>
#include <cstdint>

// LayerHypercube: out[b, f*1024+o] = sum_j x[b, o^(1<<j)] * w[f,j,o] + bias[f,o] + x[b,o]
// B=2048, F=16, O=IN=1024, BITS=10. fm[f,j,o] == o^(1<<j) (computed, not loaded).
//
// R11 = R8 (warp-private cp.async staging, no CTA barriers, SHFL for j=2..5)
//   + output via smem staging + cp.async.bulk (TMA pipe) instead of STG
//   + ROWS=64 (grid 512, single wave, amortized weight prologue)

#define BATCH   2048
#define INSZ    1024
#define OUTSZ   1024
#define NFM     16
#define NBITS   10

#define THREADS 128
#define NWARP   4
#define OG      16
#define OTILE   64
#define ROWS    64              // 32 pairs per block
#define PAIRS   (ROWS / 2)
#define OBLOCKS (OUTSZ / OTILE) // 16
#define BBLOCKS (BATCH / ROWS)  // 32
#define NBUF    3

#define CHUNK_B   256
#define ROW_B     (5 * CHUNK_B)     // 1280 B per row (5 chunks)
#define WBUF_B    (2 * ROW_B)       // 2560 B per warp in-buffer (pair)

// out-staging: per warp 2 slots x 8 segments x 256B = 4096B
#define OSLOT_B   2048
#define OWARP_B   (2 * OSLOT_B)

typedef unsigned long long ull;

__device__ __forceinline__ void cp16(uint32_t dst_smem, const void* src_gmem) {
    asm volatile("cp.async.cg.shared.global [%0], [%1], 16;\n"
                 :: "r"(dst_smem), "l"(src_gmem));
}
__device__ __forceinline__ void cp_commit() { asm volatile("cp.async.commit_group;\n"); }
__device__ __forceinline__ void cp_wait1()  { asm volatile("cp.async.wait_group 1;\n"); }

__device__ __forceinline__ void fma2(ull& d, ull a, ull b) {
    asm("fma.rn.f32x2 %0, %1, %2, %0;" : "+l"(d) : "l"(a), "l"(b));
}
__device__ __forceinline__ ull add2(ull a, ull b) {
    ull d; asm("add.rn.f32x2 %0, %1, %2;" : "=l"(d) : "l"(a), "l"(b)); return d;
}
__device__ __forceinline__ ull pk(float lo, float hi) {
    ull d; asm("mov.b64 %0, {%1, %2};" : "=l"(d) : "f"(lo), "f"(hi)); return d;
}
__device__ __forceinline__ void sts2(uint32_t addr, ull lo, ull hi) {
    asm volatile("st.shared.v2.b64 [%0], {%1, %2};" :: "r"(addr), "l"(lo), "l"(hi));
}

__global__ __launch_bounds__(THREADS, 4)
void hypercube_kernel(const float* __restrict__ x,
                      const float* __restrict__ w,
                      const float* __restrict__ bias,
                      float* __restrict__ out)
{
    __shared__ float4 sbuf[NBUF * NWARP * (WBUF_B / 16)];      // 30720 B in-stage
    __shared__ float4 obuf[NWARP * (OWARP_B / 16)];            // 16384 B out-stage

    const int tid   = threadIdx.x;
    const int lane  = tid & 31;
    const int wid   = tid >> 5;
    const int og    = tid & (OG - 1);
    const int fp    = tid >> 4;                 // 2*wid + (lane>>4)
    const int h     = lane >> 4;                // 0/1 half of warp
    const int obase = blockIdx.x * OTILE + og * 4;
    const int row0  = blockIdx.y * ROWS;
    const int B0    = blockIdx.x * OTILE;

    // ---- weights & bias -> registers as f32x2 pairs ----
    ull w0l[NBITS], w0h[NBITS], w1l[NBITS], w1h[NBITS];
#pragma unroll
    for (int j = 0; j < NBITS; j++) {
        ulonglong2 t0 = *reinterpret_cast<const ulonglong2*>(
            w + ((fp * NBITS + j) * OUTSZ + obase));
        ulonglong2 t1 = *reinterpret_cast<const ulonglong2*>(
            w + (((fp + 8) * NBITS + j) * OUTSZ + obase));
        w0l[j] = t0.x; w0h[j] = t0.y;
        w1l[j] = t1.x; w1h[j] = t1.y;
    }
    const ulonglong2 bb0 = *reinterpret_cast<const ulonglong2*>(bias + fp * OUTSZ + obase);
    const ulonglong2 bb1 = *reinterpret_cast<const ulonglong2*>(bias + (fp + 8) * OUTSZ + obase);

    // ---- warp-private in-staging: 160 16B units per pair, 5 per lane ----
    int srcOff[5];
    {
        const int tb = B0 * 4;
#pragma unroll
        for (int k = 0; k < 5; k++) {
            const int u = k * 32 + lane;
            const int r = (u >= 80) ? 1 : 0;
            const int t = u - 80 * r;
            const int c = t >> 4;
            const int i = t & 15;
            const int xorB = (c == 0) ? 0 : (256 << (c - 1));  // 0,256,512,1024,2048
            srcOff[k] = r * 4096 + (tb ^ xorB) + i * 16;
        }
    }

    const uint32_t wb0 = (uint32_t)__cvta_generic_to_shared(sbuf) + wid * WBUF_B;
    const char*    xpb = reinterpret_cast<const char*>(x + (size_t)row0 * INSZ);

    auto issue_pair = [&](int bufIdx, int pair) {
        const char* base = xpb + (size_t)pair * 8192;
        const uint32_t db = wb0 + bufIdx * (NWARP * WBUF_B) + lane * 16;
#pragma unroll
        for (int k = 0; k < 5; k++)
            cp16(db + k * 512, base + srcOff[k]);
    };

    issue_pair(0, 0); cp_commit();
    issue_pair(1, 1); cp_commit();

    // ---- out-staging geometry ----
    const uint32_t ob_w = (uint32_t)__cvta_generic_to_shared(obuf) + wid * OWARP_B;
    // per-thread STS targets within a slot: segs {h, 2+h, 4+h, 6+h}, offset og*16
    const uint32_t stsBase = ob_w + h * 256 + og * 16;

    // lanes 0..7: bulk-copy issuers; lane t -> segment t
    // gmem dst: row = row0+2s+(t>>2), fm = 2*wid + (t&1) + ((t&2)?8:0)
    float* gdst0 = nullptr;
    uint32_t osrc0 = 0;
    if (lane < 8) {
        const int fmv = 2 * wid + (lane & 1) + ((lane & 2) ? 8 : 0);
        gdst0 = out + (size_t)(row0 + (lane >> 2)) * (NFM * OUTSZ) + fmv * OUTSZ + B0;
        osrc0 = ob_w + lane * 256;
    }

    const int o1 = og ^ 1, o2 = og ^ 2, o4 = og ^ 4, o8 = og ^ 8;

    int cur = 0;
    for (int s = 0; s < PAIRS; s++) {
        cp_wait1();                       // warp-local: pair s landed

        int nxt = cur + 2; if (nxt >= NBUF) nxt -= NBUF;
        if (s + 2 < PAIRS) issue_pair(nxt, s + 2);
        cp_commit();

        const float4* rbA = sbuf + (cur * NWARP + wid) * (WBUF_B / 16);
        const float4* rbB = rbA + (ROW_B / 16);

        const float4 p = rbA[og];
        const float4 q = rbB[og];
        const ull Pl = pk(p.x, p.y), Ph = pk(p.z, p.w);
        const ull Ql = pk(q.x, q.y), Qh = pk(q.z, q.w);

        // acc = bias + tiled x
        ull a0l = add2(bb0.x, Pl), a0h = add2(bb0.y, Ph);
        ull a1l = add2(bb1.x, Pl), a1h = add2(bb1.y, Ph);
        ull c0l = add2(bb0.x, Ql), c0h = add2(bb0.y, Qh);
        ull c1l = add2(bb1.x, Ql), c1h = add2(bb1.y, Qh);

        // j=0: x[o^1] -> per-pair swap (free re-pack)
        {
            const ull Psl = pk(p.y, p.x), Psh = pk(p.w, p.z);
            const ull Qsl = pk(q.y, q.x), Qsh = pk(q.w, q.z);
            fma2(a0l, w0l[0], Psl); fma2(a0h, w0h[0], Psh);
            fma2(a1l, w1l[0], Psl); fma2(a1h, w1h[0], Psh);
            fma2(c0l, w0l[0], Qsl); fma2(c0h, w0h[0], Qsh);
            fma2(c1l, w1l[0], Qsl); fma2(c1h, w1h[0], Qsh);
        }

        // j=1: x[o^2] -> half reversal (operand order, free)
        fma2(a0l, w0l[1], Ph);  fma2(a0h, w0h[1], Pl);
        fma2(a1l, w1l[1], Ph);  fma2(a1h, w1h[1], Pl);
        fma2(c0l, w0l[1], Qh);  fma2(c0h, w0h[1], Ql);
        fma2(c1l, w1l[1], Qh);  fma2(c1h, w1h[1], Ql);

        // j=2..5: partner lane (lane^m, m=1,2,4,8) holds x[o^(4<<k)] -> shfl.bfly
#pragma unroll
        for (int k = 0; k < 4; k++) {
            const int m = 1 << k;
            const int j = k + 2;
            const float ux = __shfl_xor_sync(0xffffffffu, p.x, m);
            const float uy = __shfl_xor_sync(0xffffffffu, p.y, m);
            const float uz = __shfl_xor_sync(0xffffffffu, p.z, m);
            const float uw = __shfl_xor_sync(0xffffffffu, p.w, m);
            const float vx = __shfl_xor_sync(0xffffffffu, q.x, m);
            const float vy = __shfl_xor_sync(0xffffffffu, q.y, m);
            const float vz = __shfl_xor_sync(0xffffffffu, q.z, m);
            const float vw = __shfl_xor_sync(0xffffffffu, q.w, m);
            const ull Ulo = pk(ux, uy), Uhi = pk(uz, uw);
            const ull Vlo = pk(vx, vy), Vhi = pk(vz, vw);
            fma2(a0l, w0l[j], Ulo); fma2(a0h, w0h[j], Uhi);
            fma2(a1l, w1l[j], Ulo); fma2(a1h, w1h[j], Uhi);
            fma2(c0l, w0l[j], Vlo); fma2(c0h, w0h[j], Vhi);
            fma2(c1l, w1l[j], Vlo); fma2(c1h, w1h[j], Vhi);
        }

        // j=6..9: LDS gathers from chunks 1..4 at the SAME og (warp-own buffer)
#pragma unroll
        for (int j = 6; j < NBITS; j++) {
            const int gi = (j - 5) * 16 + og;
            const ulonglong2 U = *reinterpret_cast<const ulonglong2*>(&rbA[gi]);
            const ulonglong2 V = *reinterpret_cast<const ulonglong2*>(&rbB[gi]);
            fma2(a0l, w0l[j], U.x); fma2(a0h, w0h[j], U.y);
            fma2(a1l, w1l[j], U.x); fma2(a1h, w1h[j], U.y);
            fma2(c0l, w0l[j], V.x); fma2(c0h, w0h[j], V.y);
            fma2(c1l, w1l[j], V.x); fma2(c1h, w1h[j], V.y);
        }

        // ---- store phase: smem staging + bulk async copy to gmem ----
        const uint32_t slotOff = (s & 1) ? OSLOT_B : 0;

        // slot reused from iter s-2: its bulk reads must be done
        if (lane < 8)
            asm volatile("cp.async.bulk.wait_group.read 1;" ::: "memory");
        __syncwarp();

        {
            const uint32_t sb = stsBase + slotOff;
            sts2(sb,        a0l, a0h);    // seg h     : row A, fm 2w+h
            sts2(sb + 512,  a1l, a1h);    // seg 2+h   : row A, fm 2w+h+8
            sts2(sb + 1024, c0l, c0h);    // seg 4+h   : row B, fm 2w+h
            sts2(sb + 1536, c1l, c1h);    // seg 6+h   : row B, fm 2w+h+8
        }
        __syncwarp();

        if (lane < 8) {
            asm volatile("fence.proxy.async.shared::cta;" ::: "memory");
            float* gdst = gdst0 + (size_t)(2 * s) * (NFM * OUTSZ);
            asm volatile(
                "cp.async.bulk.global.shared::cta.bulk_group [%0], [%1], 256;"
                :: "l"(gdst), "r"(osrc0 + slotOff) : "memory");
            asm volatile("cp.async.bulk.commit_group;" ::: "memory");
        }

        cur = cur + 1; if (cur >= NBUF) cur -= NBUF;
    }
}

extern "C" void kernel_launch(void* const* d_in, const int* in_sizes, int n_in,
                              void* d_out, int out_size)
{
    const float* x    = (const float*)d_in[0];
    const float* w    = (const float*)d_in[1];
    const float* bias = (const float*)d_in[2];
    // d_in[3] = fm (int32) — values are o^(1<<j), computed inline instead.
    float* out = (float*)d_out;

    dim3 grid(OBLOCKS, BBLOCKS);
    hypercube_kernel<<<grid, THREADS>>>(x, w, bias, out);
}

// round 12
// speedup vs baseline: 1.1502x; 1.1502x over previous
#include <cuda_runtime.h>
#include <cuda_bf16.h>
#include <cstdint>

// LayerHypercube: out[b, f*1024+o] = sum_j x[b, o^(1<<j)] * w[f,j,o] + bias[f,o] + x[b,o]
// B=2048, F=16, O=IN=1024, BITS=10. fm[f,j,o] == o^(1<<j) (computed, not loaded).
//
// R12 = R8 (warp-private cp.async staging, no CTA barriers, SHFL j=2..5,
//           LDS j=6..9, f32x2 math, __stcs stores, ROWS=32, NBUF=3)
//   - chunk0 staging removed: p/q via coalesced LDG.128 (L1-shared across
//     warps/CTAs), issued before cp_wait so latency hides under the pipeline.

#define BATCH   2048
#define INSZ    1024
#define OUTSZ   1024
#define NFM     16
#define NBITS   10

#define THREADS 128
#define NWARP   4
#define OG      16
#define OTILE   64
#define ROWS    32              // 16 pairs per block
#define PAIRS   (ROWS / 2)
#define OBLOCKS (OUTSZ / OTILE) // 16
#define BBLOCKS (BATCH / ROWS)  // 64
#define NBUF    3

#define CHUNK_B   256
#define ROW_B     (4 * CHUNK_B)     // 1024 B per row (4 remote chunks)
#define WBUF_B    (2 * ROW_B)       // 2048 B per warp-buffer (pair)

typedef unsigned long long ull;

__device__ __forceinline__ void cp16(uint32_t dst_smem, const void* src_gmem) {
    asm volatile("cp.async.cg.shared.global [%0], [%1], 16;\n"
                 :: "r"(dst_smem), "l"(src_gmem));
}
__device__ __forceinline__ void cp_commit() { asm volatile("cp.async.commit_group;\n"); }
__device__ __forceinline__ void cp_wait1()  { asm volatile("cp.async.wait_group 1;\n"); }

__device__ __forceinline__ void fma2(ull& d, ull a, ull b) {
    asm("fma.rn.f32x2 %0, %1, %2, %0;" : "+l"(d) : "l"(a), "l"(b));
}
__device__ __forceinline__ ull add2(ull a, ull b) {
    ull d; asm("add.rn.f32x2 %0, %1, %2;" : "=l"(d) : "l"(a), "l"(b)); return d;
}
__device__ __forceinline__ ull pk(float lo, float hi) {
    ull d; asm("mov.b64 %0, {%1, %2};" : "=l"(d) : "f"(lo), "f"(hi)); return d;
}
__device__ __forceinline__ void stcs2(void* p, ull lo, ull hi) {
    asm volatile("st.global.cs.v2.b64 [%0], {%1, %2};" :: "l"(p), "l"(lo), "l"(hi));
}

__global__ __launch_bounds__(THREADS, 4)
void hypercube_kernel(const float* __restrict__ x,
                      const float* __restrict__ w,
                      const float* __restrict__ bias,
                      float* __restrict__ out)
{
    __shared__ float4 sbuf[NBUF * NWARP * (WBUF_B / 16)];   // 24576 B

    const int tid   = threadIdx.x;
    const int lane  = tid & 31;
    const int wid   = tid >> 5;
    const int og    = tid & (OG - 1);
    const int fp    = tid >> 4;
    const int obase = blockIdx.x * OTILE + og * 4;
    const int row0  = blockIdx.y * ROWS;
    const int B0    = blockIdx.x * OTILE;

    // ---- weights & bias -> registers as f32x2 pairs ----
    ull w0l[NBITS], w0h[NBITS], w1l[NBITS], w1h[NBITS];
#pragma unroll
    for (int j = 0; j < NBITS; j++) {
        ulonglong2 t0 = *reinterpret_cast<const ulonglong2*>(
            w + ((fp * NBITS + j) * OUTSZ + obase));
        ulonglong2 t1 = *reinterpret_cast<const ulonglong2*>(
            w + (((fp + 8) * NBITS + j) * OUTSZ + obase));
        w0l[j] = t0.x; w0h[j] = t0.y;
        w1l[j] = t1.x; w1h[j] = t1.y;
    }
    const ulonglong2 bb0 = *reinterpret_cast<const ulonglong2*>(bias + fp * OUTSZ + obase);
    const ulonglong2 bb1 = *reinterpret_cast<const ulonglong2*>(bias + (fp + 8) * OUTSZ + obase);

    // ---- warp-private staging: 128 16B units per pair (2 rows x 4 remote chunks x 16) ----
    // unit u = k*32 + lane (k=0..3). r = u>=64, t = u-64r, c = t>>4 (chunk c+1), i = t&15.
    int srcOff[4];
    {
        const int tb = B0 * 4;   // tile byte offset within a row
#pragma unroll
        for (int k = 0; k < 4; k++) {
            const int u = k * 32 + lane;
            const int r = (u >= 64) ? 1 : 0;
            const int t = u - 64 * r;
            const int c = t >> 4;              // 0..3 -> chunks 1..4
            const int i = t & 15;
            const int xorB = 256 << c;         // 256,512,1024,2048 bytes
            srcOff[k] = r * 4096 + (tb ^ xorB) + i * 16;
        }
    }

    const uint32_t wb0 = (uint32_t)__cvta_generic_to_shared(sbuf) + wid * WBUF_B;
    const char*    xpb = reinterpret_cast<const char*>(x + (size_t)row0 * INSZ);

    auto issue_pair = [&](int bufIdx, int pair) {
        const char* base = xpb + (size_t)pair * 8192;
        const uint32_t db = wb0 + bufIdx * (NWARP * WBUF_B) + lane * 16;
#pragma unroll
        for (int k = 0; k < 4; k++)
            cp16(db + k * 512, base + srcOff[k]);
    };

    issue_pair(0, 0); cp_commit();
    issue_pair(1, 1); cp_commit();

    float* op = out + (size_t)row0 * (NFM * OUTSZ) + fp * OUTSZ + obase;

    // own-value gmem pointer (coalesced across warp; L1-shared across warps/CTAs)
    const float4* xg = reinterpret_cast<const float4*>(x) + (size_t)row0 * (INSZ / 4)
                     + (B0 >> 2) + og;

    int cur = 0;
    for (int s = 0; s < PAIRS; s++) {
        // own values: independent of the cp.async pipeline -> issue before wait
        const float4 p = xg[0];
        const float4 q = xg[INSZ / 4];
        xg += 2 * (INSZ / 4);

        cp_wait1();                       // warp-local: pair s landed

        int nxt = cur + 2; if (nxt >= NBUF) nxt -= NBUF;
        if (s + 2 < PAIRS) issue_pair(nxt, s + 2);
        cp_commit();

        const float4* rbA = sbuf + (cur * NWARP + wid) * (WBUF_B / 16);
        const float4* rbB = rbA + (ROW_B / 16);

        const ull Pl = pk(p.x, p.y), Ph = pk(p.z, p.w);
        const ull Ql = pk(q.x, q.y), Qh = pk(q.z, q.w);

        // acc = bias + tiled x
        ull a0l = add2(bb0.x, Pl), a0h = add2(bb0.y, Ph);
        ull a1l = add2(bb1.x, Pl), a1h = add2(bb1.y, Ph);
        ull c0l = add2(bb0.x, Ql), c0h = add2(bb0.y, Qh);
        ull c1l = add2(bb1.x, Ql), c1h = add2(bb1.y, Qh);

        // j=0: x[o^1] -> per-pair swap (free re-pack)
        {
            const ull Psl = pk(p.y, p.x), Psh = pk(p.w, p.z);
            const ull Qsl = pk(q.y, q.x), Qsh = pk(q.w, q.z);
            fma2(a0l, w0l[0], Psl); fma2(a0h, w0h[0], Psh);
            fma2(a1l, w1l[0], Psl); fma2(a1h, w1h[0], Psh);
            fma2(c0l, w0l[0], Qsl); fma2(c0h, w0h[0], Qsh);
            fma2(c1l, w1l[0], Qsl); fma2(c1h, w1h[0], Qsh);
        }

        // j=1: x[o^2] -> half reversal (operand order, free)
        fma2(a0l, w0l[1], Ph);  fma2(a0h, w0h[1], Pl);
        fma2(a1l, w1l[1], Ph);  fma2(a1h, w1h[1], Pl);
        fma2(c0l, w0l[1], Qh);  fma2(c0h, w0h[1], Ql);
        fma2(c1l, w1l[1], Qh);  fma2(c1h, w1h[1], Ql);

        // j=2..5: partner lane (lane^m, m=1,2,4,8) holds x[o^(4<<k)] -> shfl.bfly
#pragma unroll
        for (int k = 0; k < 4; k++) {
            const int m = 1 << k;
            const int j = k + 2;
            const float ux = __shfl_xor_sync(0xffffffffu, p.x, m);
            const float uy = __shfl_xor_sync(0xffffffffu, p.y, m);
            const float uz = __shfl_xor_sync(0xffffffffu, p.z, m);
            const float uw = __shfl_xor_sync(0xffffffffu, p.w, m);
            const float vx = __shfl_xor_sync(0xffffffffu, q.x, m);
            const float vy = __shfl_xor_sync(0xffffffffu, q.y, m);
            const float vz = __shfl_xor_sync(0xffffffffu, q.z, m);
            const float vw = __shfl_xor_sync(0xffffffffu, q.w, m);
            const ull Ulo = pk(ux, uy), Uhi = pk(uz, uw);
            const ull Vlo = pk(vx, vy), Vhi = pk(vz, vw);
            fma2(a0l, w0l[j], Ulo); fma2(a0h, w0h[j], Uhi);
            fma2(a1l, w1l[j], Ulo); fma2(a1h, w1h[j], Uhi);
            fma2(c0l, w0l[j], Vlo); fma2(c0h, w0h[j], Vhi);
            fma2(c1l, w1l[j], Vlo); fma2(c1h, w1h[j], Vhi);
        }

        // j=6..9: LDS gathers from staged remote chunks 1..4 at the SAME og
#pragma unroll
        for (int j = 6; j < NBITS; j++) {
            const int gi = (j - 6) * 16 + og;
            const ulonglong2 U = *reinterpret_cast<const ulonglong2*>(&rbA[gi]);
            const ulonglong2 V = *reinterpret_cast<const ulonglong2*>(&rbB[gi]);
            fma2(a0l, w0l[j], U.x); fma2(a0h, w0h[j], U.y);
            fma2(a1l, w1l[j], U.x); fma2(a1h, w1h[j], U.y);
            fma2(c0l, w0l[j], V.x); fma2(c0h, w0h[j], V.y);
            fma2(c1l, w1l[j], V.x); fma2(c1h, w1h[j], V.y);
        }

        stcs2(op,                           a0l, a0h);
        stcs2(op + 8 * OUTSZ,               a1l, a1h);
        stcs2(op + NFM * OUTSZ,             c0l, c0h);
        stcs2(op + NFM * OUTSZ + 8 * OUTSZ, c1l, c1h);

        op += 2 * NFM * OUTSZ;
        cur = cur + 1; if (cur >= NBUF) cur -= NBUF;
    }
}

extern "C" void kernel_launch(void* const* d_in, const int* in_sizes, int n_in,
                              void* d_out, int out_size)
{
    const float* x    = (const float*)d_in[0];
    const float* w    = (const float*)d_in[1];
    const float* bias = (const float*)d_in[2];
    // d_in[3] = fm (int32) — values are o^(1<<j), computed inline instead.
    float* out = (float*)d_out;

    dim3 grid(OBLOCKS, BBLOCKS);
    hypercube_kernel<<<grid, THREADS>>>(x, w, bias, out);
}

// round 13
// speedup vs baseline: 1.5028x; 1.3066x over previous
#include <cuda_runtime.h>
#include <cuda_bf16.h>
#include <cstdint>

// LayerHypercube: out[b, f*1024+o] = sum_j x[b, o^(1<<j)] * w[f,j,o] + bias[f,o] + x[b,o]
// B=2048, F=16, O=IN=1024, BITS=10. fm[f,j,o] == o^(1<<j) (computed, not loaded).
//
// R13 = R8 compute body (SHFL j=2..5, LDS j=6..9, f32x2, __stcs, ROWS=32)
//   + phase-cooperative staging: each warp stages ONE pair per 4-pair phase,
//     one __syncthreads per phase (4 per block). LDGSTS 4x less than R8.

#define BATCH   2048
#define INSZ    1024
#define OUTSZ   1024
#define NFM     16
#define NBITS   10

#define THREADS 128
#define NWARP   4
#define OG      16
#define OTILE   64
#define ROWS    32              // 16 pairs per block
#define PAIRS   (ROWS / 2)
#define PPH     4               // pairs per phase (one per warp)
#define PHASES  (PAIRS / PPH)   // 4
#define OBLOCKS (OUTSZ / OTILE) // 16
#define BBLOCKS (BATCH / ROWS)  // 64
#define NBUF    3               // phase buffers

#define CHUNK_B   256
#define ROW_B     (5 * CHUNK_B)     // 1280 B per row (5 chunks incl. own)
#define PBUF_B    (2 * ROW_B)       // 2560 B per pair
#define PHASE_B   (PPH * PBUF_B)    // 10240 B per phase

typedef unsigned long long ull;

__device__ __forceinline__ void cp16(uint32_t dst_smem, const void* src_gmem) {
    asm volatile("cp.async.cg.shared.global [%0], [%1], 16;\n"
                 :: "r"(dst_smem), "l"(src_gmem));
}
__device__ __forceinline__ void cp_commit() { asm volatile("cp.async.commit_group;\n"); }
__device__ __forceinline__ void cp_wait1()  { asm volatile("cp.async.wait_group 1;\n"); }

__device__ __forceinline__ void fma2(ull& d, ull a, ull b) {
    asm("fma.rn.f32x2 %0, %1, %2, %0;" : "+l"(d) : "l"(a), "l"(b));
}
__device__ __forceinline__ ull add2(ull a, ull b) {
    ull d; asm("add.rn.f32x2 %0, %1, %2;" : "=l"(d) : "l"(a), "l"(b)); return d;
}
__device__ __forceinline__ ull pk(float lo, float hi) {
    ull d; asm("mov.b64 %0, {%1, %2};" : "=l"(d) : "f"(lo), "f"(hi)); return d;
}
__device__ __forceinline__ void stcs2(void* p, ull lo, ull hi) {
    asm volatile("st.global.cs.v2.b64 [%0], {%1, %2};" :: "l"(p), "l"(lo), "l"(hi));
}

__global__ __launch_bounds__(THREADS, 4)
void hypercube_kernel(const float* __restrict__ x,
                      const float* __restrict__ w,
                      const float* __restrict__ bias,
                      float* __restrict__ out)
{
    __shared__ float4 sbuf[NBUF * (PHASE_B / 16)];   // 30720 B

    const int tid   = threadIdx.x;
    const int lane  = tid & 31;
    const int wid   = tid >> 5;
    const int og    = tid & (OG - 1);
    const int fp    = tid >> 4;
    const int obase = blockIdx.x * OTILE + og * 4;
    const int row0  = blockIdx.y * ROWS;
    const int B0    = blockIdx.x * OTILE;

    // ---- weights & bias -> registers as f32x2 pairs ----
    ull w0l[NBITS], w0h[NBITS], w1l[NBITS], w1h[NBITS];
#pragma unroll
    for (int j = 0; j < NBITS; j++) {
        ulonglong2 t0 = *reinterpret_cast<const ulonglong2*>(
            w + ((fp * NBITS + j) * OUTSZ + obase));
        ulonglong2 t1 = *reinterpret_cast<const ulonglong2*>(
            w + (((fp + 8) * NBITS + j) * OUTSZ + obase));
        w0l[j] = t0.x; w0h[j] = t0.y;
        w1l[j] = t1.x; w1h[j] = t1.y;
    }
    const ulonglong2 bb0 = *reinterpret_cast<const ulonglong2*>(bias + fp * OUTSZ + obase);
    const ulonglong2 bb1 = *reinterpret_cast<const ulonglong2*>(bias + (fp + 8) * OUTSZ + obase);

    // ---- staging unit map: 160 16B units per pair, 5 per lane ----
    int srcOff[5];
    {
        const int tb = B0 * 4;   // tile byte offset within a row
#pragma unroll
        for (int k = 0; k < 5; k++) {
            const int u = k * 32 + lane;
            const int r = (u >= 80) ? 1 : 0;
            const int t = u - 80 * r;
            const int c = t >> 4;
            const int i = t & 15;
            const int xorB = (c == 0) ? 0 : (256 << (c - 1));  // 0,256,512,1024,2048
            srcOff[k] = r * 4096 + (tb ^ xorB) + i * 16;
        }
    }

    const uint32_t sbase = (uint32_t)__cvta_generic_to_shared(sbuf);
    const char*    xpb   = reinterpret_cast<const char*>(x + (size_t)row0 * INSZ);

    // warp wid stages pair (ph*PPH + wid) into slot [ph%3][wid]
    auto issue_phase = [&](int ph) {
        const char* base = xpb + (size_t)(ph * PPH + wid) * 8192;
        const uint32_t db = sbase + (ph % NBUF) * PHASE_B + wid * PBUF_B + lane * 16;
#pragma unroll
        for (int k = 0; k < 5; k++)
            cp16(db + k * 512, base + srcOff[k]);
    };

    issue_phase(0); cp_commit();
    issue_phase(1); cp_commit();

    float* op = out + (size_t)row0 * (NFM * OUTSZ) + fp * OUTSZ + obase;

    for (int ph = 0; ph < PHASES; ph++) {
        cp_wait1();            // this warp's copies for phase ph complete
        __syncthreads();       // all warps' copies complete; phase ph-1 reads done

        if (ph + 2 < PHASES) issue_phase(ph + 2);
        cp_commit();           // uniform group accounting

        const float4* pb = sbuf + (ph % NBUF) * (PHASE_B / 16);

#pragma unroll
        for (int i = 0; i < PPH; i++) {
            const float4* rbA = pb + i * (PBUF_B / 16);
            const float4* rbB = rbA + (ROW_B / 16);

            const float4 p = rbA[og];
            const float4 q = rbB[og];
            const ull Pl = pk(p.x, p.y), Ph = pk(p.z, p.w);
            const ull Ql = pk(q.x, q.y), Qh = pk(q.z, q.w);

            // acc = bias + tiled x
            ull a0l = add2(bb0.x, Pl), a0h = add2(bb0.y, Ph);
            ull a1l = add2(bb1.x, Pl), a1h = add2(bb1.y, Ph);
            ull c0l = add2(bb0.x, Ql), c0h = add2(bb0.y, Qh);
            ull c1l = add2(bb1.x, Ql), c1h = add2(bb1.y, Qh);

            // j=0: x[o^1] -> per-pair swap (free re-pack)
            {
                const ull Psl = pk(p.y, p.x), Psh = pk(p.w, p.z);
                const ull Qsl = pk(q.y, q.x), Qsh = pk(q.w, q.z);
                fma2(a0l, w0l[0], Psl); fma2(a0h, w0h[0], Psh);
                fma2(a1l, w1l[0], Psl); fma2(a1h, w1h[0], Psh);
                fma2(c0l, w0l[0], Qsl); fma2(c0h, w0h[0], Qsh);
                fma2(c1l, w1l[0], Qsl); fma2(c1h, w1h[0], Qsh);
            }

            // j=1: x[o^2] -> half reversal (operand order, free)
            fma2(a0l, w0l[1], Ph);  fma2(a0h, w0h[1], Pl);
            fma2(a1l, w1l[1], Ph);  fma2(a1h, w1h[1], Pl);
            fma2(c0l, w0l[1], Qh);  fma2(c0h, w0h[1], Ql);
            fma2(c1l, w1l[1], Qh);  fma2(c1h, w1h[1], Ql);

            // j=2..5: partner lane (lane^m, m=1,2,4,8) -> shfl.bfly
#pragma unroll
            for (int k = 0; k < 4; k++) {
                const int m = 1 << k;
                const int j = k + 2;
                const float ux = __shfl_xor_sync(0xffffffffu, p.x, m);
                const float uy = __shfl_xor_sync(0xffffffffu, p.y, m);
                const float uz = __shfl_xor_sync(0xffffffffu, p.z, m);
                const float uw = __shfl_xor_sync(0xffffffffu, p.w, m);
                const float vx = __shfl_xor_sync(0xffffffffu, q.x, m);
                const float vy = __shfl_xor_sync(0xffffffffu, q.y, m);
                const float vz = __shfl_xor_sync(0xffffffffu, q.z, m);
                const float vw = __shfl_xor_sync(0xffffffffu, q.w, m);
                const ull Ulo = pk(ux, uy), Uhi = pk(uz, uw);
                const ull Vlo = pk(vx, vy), Vhi = pk(vz, vw);
                fma2(a0l, w0l[j], Ulo); fma2(a0h, w0h[j], Uhi);
                fma2(a1l, w1l[j], Ulo); fma2(a1h, w1h[j], Uhi);
                fma2(c0l, w0l[j], Vlo); fma2(c0h, w0h[j], Vhi);
                fma2(c1l, w1l[j], Vlo); fma2(c1h, w1h[j], Vhi);
            }

            // j=6..9: LDS gathers from chunks 1..4 at the SAME og
#pragma unroll
            for (int j = 6; j < NBITS; j++) {
                const int gi = (j - 5) * 16 + og;
                const ulonglong2 U = *reinterpret_cast<const ulonglong2*>(&rbA[gi]);
                const ulonglong2 V = *reinterpret_cast<const ulonglong2*>(&rbB[gi]);
                fma2(a0l, w0l[j], U.x); fma2(a0h, w0h[j], U.y);
                fma2(a1l, w1l[j], U.x); fma2(a1h, w1h[j], U.y);
                fma2(c0l, w0l[j], V.x); fma2(c0h, w0h[j], V.y);
                fma2(c1l, w1l[j], V.x); fma2(c1h, w1h[j], V.y);
            }

            stcs2(op,                           a0l, a0h);
            stcs2(op + 8 * OUTSZ,               a1l, a1h);
            stcs2(op + NFM * OUTSZ,             c0l, c0h);
            stcs2(op + NFM * OUTSZ + 8 * OUTSZ, c1l, c1h);

            op += 2 * NFM * OUTSZ;
        }
    }
}

extern "C" void kernel_launch(void* const* d_in, const int* in_sizes, int n_in,
                              void* d_out, int out_size)
{
    const float* x    = (const float*)d_in[0];
    const float* w    = (const float*)d_in[1];
    const float* bias = (const float*)d_in[2];
    // d_in[3] = fm (int32) — values are o^(1<<j), computed inline instead.
    float* out = (float*)d_out;

    dim3 grid(OBLOCKS, BBLOCKS);
    hypercube_kernel<<<grid, THREADS>>>(x, w, bias, out);
}

// round 14
// speedup vs baseline: 1.6163x; 1.0755x over previous
#include <cuda_runtime.h>
#include <cuda_bf16.h>
#include <cstdint>

// LayerHypercube: out[b, f*1024+o] = sum_j x[b, o^(1<<j)] * w[f,j,o] + bias[f,o] + x[b,o]
// B=2048, F=16, O=IN=1024, BITS=10. fm[f,j,o] == o^(1<<j) (computed, not loaded).
//
// R14 = R13 phase-cooperative staging (4 pairs/phase, 1 barrier/phase, NBUF=3)
//   + thread = 2 o x 4 fm: warp spans the whole 64-o tile for one fm-quad.
//     j=0 free swap; j=1..5 shfl.bfly (masks 1,2,4,8,16); j=6..9 LDS.64 from
//     staged remote chunks. Halves LDS delivered bytes vs R13.

#define BATCH   2048
#define INSZ    1024
#define OUTSZ   1024
#define NFM     16
#define NBITS   10

#define THREADS 128
#define NWARP   4
#define OTILE   64
#define ROWS    32              // 16 pairs per block
#define PAIRS   (ROWS / 2)
#define PPH     4               // pairs per phase (one per warp)
#define PHASES  (PAIRS / PPH)   // 4
#define OBLOCKS (OUTSZ / OTILE) // 16
#define BBLOCKS (BATCH / ROWS)  // 64
#define NBUF    3               // phase buffers

#define CHUNK_B   256
#define ROW_B     (5 * CHUNK_B)     // 1280 B per row (own + 4 remote chunks)
#define PBUF_B    (2 * ROW_B)       // 2560 B per pair
#define PHASE_B   (PPH * PBUF_B)    // 10240 B per phase

typedef unsigned long long ull;

__device__ __forceinline__ void cp16(uint32_t dst_smem, const void* src_gmem) {
    asm volatile("cp.async.cg.shared.global [%0], [%1], 16;\n"
                 :: "r"(dst_smem), "l"(src_gmem));
}
__device__ __forceinline__ void cp_commit() { asm volatile("cp.async.commit_group;\n"); }
__device__ __forceinline__ void cp_wait1()  { asm volatile("cp.async.wait_group 1;\n"); }

__device__ __forceinline__ void fma2(ull& d, ull a, ull b) {
    asm("fma.rn.f32x2 %0, %1, %2, %0;" : "+l"(d) : "l"(a), "l"(b));
}
__device__ __forceinline__ ull add2(ull a, ull b) {
    ull d; asm("add.rn.f32x2 %0, %1, %2;" : "=l"(d) : "l"(a), "l"(b)); return d;
}
__device__ __forceinline__ ull pk(float lo, float hi) {
    ull d; asm("mov.b64 %0, {%1, %2};" : "=l"(d) : "f"(lo), "f"(hi)); return d;
}
__device__ __forceinline__ void stcs1(void* p, ull v) {
    asm volatile("st.global.cs.b64 [%0], %1;" :: "l"(p), "l"(v));
}

__global__ __launch_bounds__(THREADS, 4)
void hypercube_kernel(const float* __restrict__ x,
                      const float* __restrict__ w,
                      const float* __restrict__ bias,
                      float* __restrict__ out)
{
    __shared__ float4 sbuf[NBUF * (PHASE_B / 16)];   // 30720 B

    const int tid   = threadIdx.x;
    const int lane  = tid & 31;
    const int wid   = tid >> 5;
    const int o2    = lane;            // o-pair index within the tile (0..31)
    const int fq    = wid;             // fm quad: fm = 4*fq + m
    const int row0  = blockIdx.y * ROWS;
    const int B0    = blockIdx.x * OTILE;
    const int ob2   = B0 + o2 * 2;     // this thread's o base (2 consecutive o)

    // ---- weights & bias -> registers as f32x2 (80 + 8 regs) ----
    ull wf[4][NBITS];
    ull bb[4];
#pragma unroll
    for (int m = 0; m < 4; m++) {
        const int fm = 4 * fq + m;
#pragma unroll
        for (int j = 0; j < NBITS; j++)
            wf[m][j] = *reinterpret_cast<const ull*>(w + ((fm * NBITS + j) * OUTSZ + ob2));
        bb[m] = *reinterpret_cast<const ull*>(bias + fm * OUTSZ + ob2);
    }

    // ---- staging unit map (identical to R13): 160 16B units/pair, 5 per lane ----
    int srcOff[5];
    {
        const int tb = B0 * 4;   // tile byte offset within a row
#pragma unroll
        for (int k = 0; k < 5; k++) {
            const int u = k * 32 + lane;
            const int r = (u >= 80) ? 1 : 0;
            const int t = u - 80 * r;
            const int c = t >> 4;
            const int i = t & 15;
            const int xorB = (c == 0) ? 0 : (256 << (c - 1));  // 0,256,512,1024,2048 B
            srcOff[k] = r * 4096 + (tb ^ xorB) + i * 16;
        }
    }

    const uint32_t sbase = (uint32_t)__cvta_generic_to_shared(sbuf);
    const char*    xpb   = reinterpret_cast<const char*>(x + (size_t)row0 * INSZ);

    // warp wid stages pair (ph*PPH + wid) into slot [ph%3][wid]
    auto issue_phase = [&](int ph) {
        const char* base = xpb + (size_t)(ph * PPH + wid) * 8192;
        const uint32_t db = sbase + (ph % NBUF) * PHASE_B + wid * PBUF_B + lane * 16;
#pragma unroll
        for (int k = 0; k < 5; k++)
            cp16(db + k * 512, base + srcOff[k]);
    };

    issue_phase(0); cp_commit();
    issue_phase(1); cp_commit();

    // output pointer: rowA, fm=4*fq, o=ob2. fm offsets are +m*1024 floats,
    // row B is +16384 floats; advance 2 rows per pair.
    float* op = out + (size_t)row0 * (NFM * OUTSZ) + (4 * fq) * OUTSZ + ob2;

    for (int ph = 0; ph < PHASES; ph++) {
        cp_wait1();            // this warp's copies for phase ph complete
        __syncthreads();       // all warps' copies complete; phase ph-1 reads done

        if (ph + 2 < PHASES) issue_phase(ph + 2);
        cp_commit();           // uniform group accounting

        const char* pb = reinterpret_cast<const char*>(sbuf) + (ph % NBUF) * PHASE_B;

#pragma unroll
        for (int i = 0; i < PPH; i++) {
            const char* rbA = pb + i * PBUF_B;          // row A chunks
            const char* rbB = rbA + ROW_B;              // row B chunks

            // own float2 (chunk 0)
            const float2 p = *reinterpret_cast<const float2*>(rbA + o2 * 8);
            const float2 q = *reinterpret_cast<const float2*>(rbB + o2 * 8);
            const ull P = pk(p.x, p.y), Q = pk(q.x, q.y);
            const ull Psw = pk(p.y, p.x), Qsw = pk(q.y, q.x);

            // acc = bias + tiled x ; then j=0 (x[o^1] = swapped own pair)
            ull a[4], c[4];
#pragma unroll
            for (int m = 0; m < 4; m++) {
                a[m] = add2(bb[m], P);
                c[m] = add2(bb[m], Q);
                fma2(a[m], wf[m][0], Psw);
                fma2(c[m], wf[m][0], Qsw);
            }

            // j=1..5: lane XOR 1,2,4,8,16 -> shfl.bfly of own float2
#pragma unroll
            for (int j = 1; j < 6; j++) {
                const int msk = 1 << (j - 1);
                const float ux = __shfl_xor_sync(0xffffffffu, p.x, msk);
                const float uy = __shfl_xor_sync(0xffffffffu, p.y, msk);
                const float vx = __shfl_xor_sync(0xffffffffu, q.x, msk);
                const float vy = __shfl_xor_sync(0xffffffffu, q.y, msk);
                const ull U = pk(ux, uy), V = pk(vx, vy);
#pragma unroll
                for (int m = 0; m < 4; m++) {
                    fma2(a[m], wf[m][j], U);
                    fma2(c[m], wf[m][j], V);
                }
            }

            // j=6..9: LDS.64 from staged remote chunks 1..4 at the same o2
#pragma unroll
            for (int j = 6; j < NBITS; j++) {
                const int cb = (j - 5) * CHUNK_B;
                const ull U = *reinterpret_cast<const ull*>(rbA + cb + o2 * 8);
                const ull V = *reinterpret_cast<const ull*>(rbB + cb + o2 * 8);
#pragma unroll
                for (int m = 0; m < 4; m++) {
                    fma2(a[m], wf[m][j], U);
                    fma2(c[m], wf[m][j], V);
                }
            }

            // stores: 8 x STG.64, each perfectly coalesced across the warp
#pragma unroll
            for (int m = 0; m < 4; m++) {
                stcs1(op + m * OUTSZ,              a[m]);
                stcs1(op + NFM * OUTSZ + m * OUTSZ, c[m]);
            }

            op += 2 * NFM * OUTSZ;
        }
    }
}

extern "C" void kernel_launch(void* const* d_in, const int* in_sizes, int n_in,
                              void* d_out, int out_size)
{
    const float* x    = (const float*)d_in[0];
    const float* w    = (const float*)d_in[1];
    const float* bias = (const float*)d_in[2];
    // d_in[3] = fm (int32) — values are o^(1<<j), computed inline instead.
    float* out = (float*)d_out;

    dim3 grid(OBLOCKS, BBLOCKS);
    hypercube_kernel<<<grid, THREADS>>>(x, w, bias, out);
}